// round 6
// baseline (speedup 1.0000x reference)
#include <cuda_runtime.h>
#include <cuda_bf16.h>

// Scratch (allocation-free rule: __device__ globals).
#define MAX_S 262144
#define MAX_N 2097152
__device__ int      g_count[MAX_S];
__device__ int      g_base[MAX_S];
__device__ int      g_cursor[MAX_S];
__device__ int      g_bsum[1024];
__device__ unsigned g_last[MAX_S];    // bit pattern of segment-max timestamp (all t > 0)
__device__ int2     g_pack[MAX_N];    // {row index, weight bits}, grouped by segment

#define BETA 0.8f
#define SCAN_B 1024

// ---------------------------------------------------------------------------
__global__ void twma_init_kernel(int S) {
    int i = blockIdx.x * blockDim.x + threadIdx.x;
    if (i < S) {
        g_count[i] = 0;
        g_last[i]  = 0u;
    }
}

// Histogram of segment ids + segment-max of timestamps (uint order == float
// order since all t > 0; init 0 => empty segments output last_t = 0, matching
// the reference's where(tw>0, last_t, 0)).
__global__ void twma_hist_kernel(const int* __restrict__ ids,
                                 const float* __restrict__ ts,
                                 int N) {
    int i = blockIdx.x * blockDim.x + threadIdx.x;
    if (i < N) {
        int s = ids[i];
        atomicAdd(&g_count[s], 1);
        atomicMax(&g_last[s], __float_as_uint(ts[i]));
    }
}

// ---------------------------------------------------------------------------
// Exclusive scan of g_count -> g_base (3 kernels).
__global__ void twma_scan1_kernel(int S) {
    __shared__ int sh[SCAN_B];
    int tid = threadIdx.x;
    int gid = blockIdx.x * SCAN_B + tid;
    int v = (gid < S) ? g_count[gid] : 0;
    sh[tid] = v;
    __syncthreads();
    for (int off = 1; off < SCAN_B; off <<= 1) {
        int t = (tid >= off) ? sh[tid - off] : 0;
        __syncthreads();
        sh[tid] += t;
        __syncthreads();
    }
    int incl = sh[tid];
    if (gid < S) g_base[gid] = incl - v;          // exclusive
    if (tid == SCAN_B - 1) g_bsum[blockIdx.x] = incl;
}

// Syncfree single-warp shuffle scan of the <=64 block sums (2 values/lane).
__global__ void twma_scan2_kernel(int nb) {
    int lane = threadIdx.x;                       // 32 threads
    int v0 = (lane      < nb) ? g_bsum[lane]      : 0;
    int v1 = (lane + 32 < nb) ? g_bsum[lane + 32] : 0;
    int s0 = v0, s1 = v1;
    #pragma unroll
    for (int off = 1; off < 32; off <<= 1) {
        int t0 = __shfl_up_sync(0xffffffffu, s0, off);
        int t1 = __shfl_up_sync(0xffffffffu, s1, off);
        if (lane >= off) { s0 += t0; s1 += t1; }
    }
    int tot0 = __shfl_sync(0xffffffffu, s0, 31);  // sum of first 32
    if (lane      < nb) g_bsum[lane]      = s0 - v0;          // exclusive
    if (lane + 32 < nb) g_bsum[lane + 32] = s1 - v1 + tot0;
}

__global__ void twma_scan3_kernel(int S) {
    int gid = blockIdx.x * SCAN_B + threadIdx.x;
    if (gid < S) {
        int b = g_base[gid] + g_bsum[blockIdx.x];
        g_base[gid]   = b;
        g_cursor[gid] = b;
    }
}

// ---------------------------------------------------------------------------
// Bucket rows by segment AND precompute the decay weight per row (last_t is
// final by this point). One 8-byte store carries both the row index and the
// weight bits, so the gather loop needs a single broadcast LDG.64 per row.
__global__ void twma_scatter_kernel(const int*   __restrict__ ids,
                                    const float* __restrict__ ts,
                                    int N) {
    int i = blockIdx.x * blockDim.x + threadIdx.x;
    if (i < N) {
        int   s  = ids[i];
        float lt = __uint_as_float(g_last[s]);
        float w  = __expf(BETA * (ts[i] - lt));   // w in (0, 1]
        int p = atomicAdd(&g_cursor[s], 1);
        g_pack[p] = make_int2(i, __float_as_int(w));
    }
}

// ---------------------------------------------------------------------------
// One warp per (segment, 128-float column tile): gather the segment's rows,
// accumulate w*m in registers, write agg = acc/tw and last_t exactly once.
// Loop body: one broadcast LDG.64 (pack) + one coalesced-512B-per-warp
// LDG.128 gather + 5 FMAs. Unroll 8 => 8 independent gathers in flight.
__global__ void twma_seg_kernel(const float4* __restrict__ msg,
                                float* __restrict__ out,
                                int S, int C /* D/4 */, int D) {
    int gw   = (blockIdx.x * blockDim.x + threadIdx.x) >> 5;
    int lane = threadIdx.x & 31;
    int tilesPerSeg = C >> 5;                 // D/128 column tiles (2 for D=256)
    int seg  = gw / tilesPerSeg;
    int tile = gw - seg * tilesPerSeg;
    if (seg >= S) return;

    int      base = g_base[seg];
    int      cnt  = g_count[seg];
    unsigned lb   = g_last[seg];
    int      col  = (tile << 5) + lane;       // float4 index within row

    float4 acc = make_float4(0.f, 0.f, 0.f, 0.f);
    float  tw  = 0.f;

    #pragma unroll 8
    for (int r = 0; r < cnt; r++) {
        int2  pk = g_pack[base + r];          // broadcast, contiguous across r
        float w  = __int_as_float(pk.y);
        tw += w;
        float4 m = msg[(long long)pk.x * C + col];
        acc.x += w * m.x;
        acc.y += w * m.y;
        acc.z += w * m.z;
        acc.w += w * m.w;
    }

    float inv = (cnt > 0) ? (1.0f / tw) : 0.0f;
    reinterpret_cast<float4*>(out)[(long long)seg * C + col] =
        make_float4(acc.x * inv, acc.y * inv, acc.z * inv, acc.w * inv);

    if (tile == 0 && lane == 0) {
        out[(long long)S * D + seg] = __uint_as_float(lb);  // 0 for empty segs
    }
}

// ---------------------------------------------------------------------------
extern "C" void kernel_launch(void* const* d_in, const int* in_sizes, int n_in,
                              void* d_out, int out_size) {
    const float* msg = (const float*)d_in[0];   // [N, D] fp32
    const float* ts  = (const float*)d_in[1];   // [N]    fp32
    const int*   ids = (const int*)d_in[2];     // [N]    int32

    int N = in_sizes[1];
    int D = in_sizes[0] / N;          // 256
    int S = out_size / (D + 1);       // 65536 (out = S*D agg + S last_t)
    int C = D / 4;

    float* out = (float*)d_out;

    twma_init_kernel<<<(S + 255) / 256, 256>>>(S);
    twma_hist_kernel<<<(N + 255) / 256, 256>>>(ids, ts, N);

    int nb = (S + SCAN_B - 1) / SCAN_B;         // 64 for S=65536 (<=64 assumed)
    twma_scan1_kernel<<<nb, SCAN_B>>>(S);
    twma_scan2_kernel<<<1, 32>>>(nb);
    twma_scan3_kernel<<<nb, SCAN_B>>>(S);

    twma_scatter_kernel<<<(N + 255) / 256, 256>>>(ids, ts, N);

    long long warps   = (long long)S * (C >> 5);  // one warp per (seg, tile)
    long long threads = warps * 32;
    unsigned blocks   = (unsigned)((threads + 255) / 256);
    twma_seg_kernel<<<blocks, 256>>>((const float4*)msg, out, S, C, D);
}